// round 2
// baseline (speedup 1.0000x reference)
#include <cuda_runtime.h>

#define NN   65536      // total nodes
#define PP   1024       // nodes per graph
#define BB   64         // graphs
#define HH   32         // hidden dim
#define DIN  16         // input feature dim
#define EE   2097152    // edges (N*32)

// Scratch (device globals; no allocation allowed)
__device__ __align__(16) int   d_cnt[NN];        // in-degree (w/o self loop)
__device__ __align__(16) int   d_rowptr[NN + 1];
__device__ __align__(16) int   d_cursor[NN];
__device__ __align__(16) int   d_csr[EE];        // src indices binned by dst
__device__ __align__(16) float d_G [NN * HH];    // layer-1 messages g = (xW1)*dis
__device__ __align__(16) float d_G2[NN * HH];    // layer-2 messages
__device__ __align__(16) float d_pool[BB * HH];

// ---------------------------------------------------------------- zero
__global__ void k_zero(int n) {
    int i = blockIdx.x * blockDim.x + threadIdx.x;
    if (i < n) d_cnt[i] = 0;
    if (i < BB * HH) d_pool[i] = 0.0f;
}

// ---------------------------------------------------------------- count in-degree
__global__ void k_count(const int* __restrict__ dst, int e) {
    int i = blockIdx.x * blockDim.x + threadIdx.x;
    if (i < e) atomicAdd(&d_cnt[dst[i]], 1);
}

// ---------------------------------------------------------------- exclusive scan (1 CTA, 1024 thr, 64 items each)
__global__ void k_scan() {
    __shared__ int ssum[1024];
    int t = threadIdx.x;
    int base = t * 64;
    int s = 0;
#pragma unroll 8
    for (int i = 0; i < 64; i++) s += d_cnt[base + i];
    ssum[t] = s;
    __syncthreads();
    // inclusive Hillis-Steele scan over 1024 partials
    for (int off = 1; off < 1024; off <<= 1) {
        int v = (t >= off) ? ssum[t - off] : 0;
        __syncthreads();
        ssum[t] += v;
        __syncthreads();
    }
    int run = (t == 0) ? 0 : ssum[t - 1];
#pragma unroll 8
    for (int i = 0; i < 64; i++) {
        d_rowptr[base + i] = run;
        d_cursor[base + i] = run;
        run += d_cnt[base + i];
    }
    if (t == 1023) d_rowptr[NN] = run;
}

// ---------------------------------------------------------------- fill CSR
__global__ void k_fill(const int* __restrict__ src, const int* __restrict__ dst, int e) {
    int i = blockIdx.x * blockDim.x + threadIdx.x;
    if (i >= e) return;
    int d = dst[i];
    int pos = atomicAdd(&d_cursor[d], 1);
    d_csr[pos] = src[i];
}

// ---------------------------------------------------------------- G = (x @ W1^T) * dis
__global__ void k_pre1(const float* __restrict__ x, const float* __restrict__ W1, int n) {
    __shared__ float sW[HH * DIN];
    for (int i = threadIdx.x; i < HH * DIN; i += blockDim.x) sW[i] = W1[i];
    __syncthreads();
    int nd = blockIdx.x * blockDim.x + threadIdx.x;
    if (nd >= n) return;
    float xv[DIN];
    const float4* xp = (const float4*)(x + (size_t)nd * DIN);
#pragma unroll
    for (int i = 0; i < DIN / 4; i++) {
        float4 t = xp[i];
        xv[4*i] = t.x; xv[4*i+1] = t.y; xv[4*i+2] = t.z; xv[4*i+3] = t.w;
    }
    float dis = rsqrtf((float)d_cnt[nd] + 1.0f);
    float4* gp = (float4*)(d_G + (size_t)nd * HH);
#pragma unroll
    for (int jq = 0; jq < HH / 4; jq++) {
        float4 v;
        float* vp = (float*)&v;
#pragma unroll
        for (int j = 0; j < 4; j++) {
            float a = 0.f;
#pragma unroll
            for (int i = 0; i < DIN; i++) a = fmaf(xv[i], sW[(jq*4+j) * DIN + i], a);
            vp[j] = a * dis;
        }
        gp[jq] = v;
    }
}

// ---------------------------------------------------------------- layer-1 gather + fused mid transform
// warp per node: acc = g[node] + sum_{s in N(node)} g[s]
// t = tanh(dis*acc + b1);  G2 = (t @ W2^T) * dis
__global__ void k_gmid(const float* __restrict__ b1, const float* __restrict__ W2) {
    __shared__ float sWt[HH * HH];   // transposed: sWt[k*32+j] = W2[j*32+k]
    __shared__ float sb[HH];
    __shared__ float st[32 * HH];    // one t-row per warp
    for (int i = threadIdx.x; i < HH * HH; i += blockDim.x)
        sWt[(i % HH) * HH + (i / HH)] = W2[i];
    if (threadIdx.x < HH) sb[threadIdx.x] = b1[threadIdx.x];
    __syncthreads();

    int wid  = threadIdx.x >> 5;
    int lane = threadIdx.x & 31;
    int node = blockIdx.x * 32 + wid;

    int start = d_rowptr[node];
    int end   = d_rowptr[node + 1];
    float dis = rsqrtf((float)(end - start) + 1.0f);
    float acc = d_G[(size_t)node * HH + lane];     // self loop

    for (int b = start; b < end; b += 32) {
        int j = b + lane;
        int idx = (j < end) ? d_csr[j] : 0;
        int m = end - b; if (m > 32) m = 32;
        if (m == 32) {
#pragma unroll 8
            for (int k = 0; k < 32; k++) {
                int s = __shfl_sync(0xffffffffu, idx, k);
                acc += d_G[(size_t)s * HH + lane];
            }
        } else {
            for (int k = 0; k < m; k++) {
                int s = __shfl_sync(0xffffffffu, idx, k);
                acc += d_G[(size_t)s * HH + lane];
            }
        }
    }

    float t = tanhf(fmaf(dis, acc, sb[lane]));
    st[wid * HH + lane] = t;
    __syncwarp();
    float g = 0.f;
#pragma unroll
    for (int k = 0; k < HH; k++)
        g = fmaf(st[wid * HH + k], sWt[k * HH + lane], g);
    d_G2[(size_t)node * HH + lane] = g * dis;
}

// ---------------------------------------------------------------- layer-2 gather + post transform + pool
__global__ void k_gpost(const float* __restrict__ b2, const float* __restrict__ Wl,
                        const float* __restrict__ bl) {
    __shared__ float sWt[HH * HH];
    __shared__ float sb2[HH];
    __shared__ float sbl[HH];
    __shared__ float st[32 * HH];
    __shared__ float spool[HH];
    for (int i = threadIdx.x; i < HH * HH; i += blockDim.x)
        sWt[(i % HH) * HH + (i / HH)] = Wl[i];
    if (threadIdx.x < HH) {
        sb2[threadIdx.x] = b2[threadIdx.x];
        sbl[threadIdx.x] = bl[threadIdx.x];
        spool[threadIdx.x] = 0.f;
    }
    __syncthreads();

    int wid  = threadIdx.x >> 5;
    int lane = threadIdx.x & 31;
    int node = blockIdx.x * 32 + wid;

    int start = d_rowptr[node];
    int end   = d_rowptr[node + 1];
    float dis = rsqrtf((float)(end - start) + 1.0f);
    float acc = d_G2[(size_t)node * HH + lane];

    for (int b = start; b < end; b += 32) {
        int j = b + lane;
        int idx = (j < end) ? d_csr[j] : 0;
        int m = end - b; if (m > 32) m = 32;
        if (m == 32) {
#pragma unroll 8
            for (int k = 0; k < 32; k++) {
                int s = __shfl_sync(0xffffffffu, idx, k);
                acc += d_G2[(size_t)s * HH + lane];
            }
        } else {
            for (int k = 0; k < m; k++) {
                int s = __shfl_sync(0xffffffffu, idx, k);
                acc += d_G2[(size_t)s * HH + lane];
            }
        }
    }

    float u = tanhf(fmaf(dis, acc, sb2[lane]));
    st[wid * HH + lane] = u;
    __syncwarp();
    float a = sbl[lane];
#pragma unroll
    for (int k = 0; k < HH; k++)
        a = fmaf(st[wid * HH + k], sWt[k * HH + lane], a);
    float v = tanhf(a);
    atomicAdd(&spool[lane], v);          // CTA-local reduction
    __syncthreads();
    if (threadIdx.x < HH) {
        int g = node >> 10;              // all 32 nodes of this CTA share one graph
        atomicAdd(&d_pool[g * HH + threadIdx.x], spool[threadIdx.x]);
    }
}

// ---------------------------------------------------------------- heads (tiny)
__global__ void k_head(const float* __restrict__ share,
                       const float* __restrict__ Wp, const float* __restrict__ bp,
                       const float* __restrict__ Vw1, const float* __restrict__ Vb1,
                       const float* __restrict__ Vw2, const float* __restrict__ Vb2,
                       const float* __restrict__ Vw3, const float* __restrict__ Vb3,
                       const float* __restrict__ Cw1, const float* __restrict__ Cb1,
                       const float* __restrict__ Cw2, const float* __restrict__ Cb2,
                       float* __restrict__ out) {
    int b = threadIdx.x;
    if (b >= BB) return;
    float p[HH];
#pragma unroll
    for (int k = 0; k < HH; k++) p[k] = d_pool[b * HH + k];
    float h1[HH];
#pragma unroll
    for (int j = 0; j < HH; j++) {
        float a = bp[j];
#pragma unroll
        for (int k = 0; k < HH; k++) a = fmaf(p[k], Wp[j * HH + k], a);
        h1[j] = a;
    }
    float s[2 * HH];
#pragma unroll
    for (int k = 0; k < 2 * HH; k++) s[k] = share[b * 2 * HH + k];
    float a1[HH];
#pragma unroll
    for (int j = 0; j < HH; j++) {
        float a = Vb1[j];
#pragma unroll
        for (int k = 0; k < 2 * HH; k++) a = fmaf(s[k], Vw1[j * 2 * HH + k], a);
        a1[j] = tanhf(a);
    }
    float a2[HH];
#pragma unroll
    for (int j = 0; j < HH; j++) {
        float a = Vb2[j];
#pragma unroll
        for (int k = 0; k < HH; k++) a = fmaf(a1[k], Vw2[j * HH + k], a);
        a2[j] = tanhf(a);
    }
    float h2[HH];
#pragma unroll
    for (int j = 0; j < HH; j++) {
        float a = Vb3[j];
#pragma unroll
        for (int k = 0; k < HH; k++) a = fmaf(a2[k], Vw3[j * HH + k], a);
        h2[j] = a;
    }
    float val = Cb2[0];
#pragma unroll
    for (int j = 0; j < HH; j++) {
        float a = Cb1[j];
#pragma unroll
        for (int k = 0; k < HH; k++) a = fmaf(h1[k], Cw1[j * 2 * HH + k], a);
#pragma unroll
        for (int k = 0; k < HH; k++) a = fmaf(h2[k], Cw1[j * 2 * HH + HH + k], a);
        val = fmaf(tanhf(a), Cw2[j], val);
    }
    out[b] = val;
}

extern "C" void kernel_launch(void* const* d_in, const int* in_sizes, int n_in,
                              void* d_out, int out_size) {
    const float* x     = (const float*)d_in[0];
    const int*   ei    = (const int*)  d_in[1];
    const float* share = (const float*)d_in[3];
    const float* W1  = (const float*)d_in[4];
    const float* b1  = (const float*)d_in[5];
    const float* W2  = (const float*)d_in[6];
    const float* b2  = (const float*)d_in[7];
    const float* Wl  = (const float*)d_in[8];
    const float* bl  = (const float*)d_in[9];
    const float* Wp  = (const float*)d_in[10];
    const float* bp  = (const float*)d_in[11];
    const float* Vw1 = (const float*)d_in[12];
    const float* Vb1 = (const float*)d_in[13];
    const float* Vw2 = (const float*)d_in[14];
    const float* Vb2 = (const float*)d_in[15];
    const float* Vw3 = (const float*)d_in[16];
    const float* Vb3 = (const float*)d_in[17];
    const float* Cw1 = (const float*)d_in[18];
    const float* Cb1 = (const float*)d_in[19];
    const float* Cw2 = (const float*)d_in[20];
    const float* Cb2 = (const float*)d_in[21];

    int n = in_sizes[0] / DIN;          // 65536
    int e = in_sizes[1] / 2;            // 2097152
    const int* src = ei;
    const int* dst = ei + e;

    int nb = (n + 255) / 256;
    int eb = (e + 255) / 256;

    k_zero <<<nb, 256>>>(n);
    k_count<<<eb, 256>>>(dst, e);
    k_scan <<<1, 1024>>>();
    k_fill <<<eb, 256>>>(src, dst, e);
    k_pre1 <<<nb, 256>>>(x, W1, n);
    k_gmid <<<n / 32, 1024>>>(b1, W2);
    k_gpost<<<n / 32, 1024>>>(b2, Wl, bl);
    k_head <<<1, 64>>>(share, Wp, bp, Vw1, Vb1, Vw2, Vb2, Vw3, Vb3,
                       Cw1, Cb1, Cw2, Cb2, (float*)d_out);
}

// round 3
// speedup vs baseline: 1.5862x; 1.5862x over previous
#include <cuda_runtime.h>

#define NN   65536      // total nodes
#define PP   1024       // nodes per graph
#define BB   64         // graphs
#define HH   32         // hidden dim
#define DIN  16         // input feature dim
#define EE   2097152    // edges (N*32)

// Scratch (device globals; no allocation allowed)
__device__ __align__(16) int   d_cnt[NN];        // in-degree (w/o self loop)
__device__ __align__(16) int   d_rowptr[NN + 1];
__device__ __align__(16) int   d_cursor[NN];
__device__ __align__(16) int   d_csr[EE];        // src indices binned by dst
__device__ __align__(16) float d_G [NN * HH];    // layer-1 messages g = (xW1)*dis
__device__ __align__(16) float d_G2[NN * HH];    // layer-2 messages
__device__ __align__(16) float d_pool[BB * HH];

// ---------------------------------------------------------------- zero
__global__ void k_zero(int n) {
    int i = blockIdx.x * blockDim.x + threadIdx.x;
    if (i < n) d_cnt[i] = 0;
    if (i < BB * HH) d_pool[i] = 0.0f;
}

// ---------------------------------------------------------------- count in-degree
__global__ void k_count(const int* __restrict__ dst, int e) {
    int i = blockIdx.x * blockDim.x + threadIdx.x;
    if (i < e) atomicAdd(&d_cnt[dst[i]], 1);
}

// ---------------------------------------------------------------- exclusive scan (1 CTA, 1024 thr, 64 items each)
__global__ void k_scan() {
    __shared__ int ssum[1024];
    int t = threadIdx.x;
    int base = t * 64;
    int s = 0;
#pragma unroll 8
    for (int i = 0; i < 64; i++) s += d_cnt[base + i];
    ssum[t] = s;
    __syncthreads();
    for (int off = 1; off < 1024; off <<= 1) {
        int v = (t >= off) ? ssum[t - off] : 0;
        __syncthreads();
        ssum[t] += v;
        __syncthreads();
    }
    int run = (t == 0) ? 0 : ssum[t - 1];
#pragma unroll 8
    for (int i = 0; i < 64; i++) {
        d_rowptr[base + i] = run;
        d_cursor[base + i] = run;
        run += d_cnt[base + i];
    }
    if (t == 1023) d_rowptr[NN] = run;
}

// ---------------------------------------------------------------- fill CSR
__global__ void k_fill(const int* __restrict__ src, const int* __restrict__ dst, int e) {
    int i = blockIdx.x * blockDim.x + threadIdx.x;
    if (i >= e) return;
    int d = dst[i];
    int pos = atomicAdd(&d_cursor[d], 1);
    d_csr[pos] = src[i];
}

// ---------------------------------------------------------------- G = (x @ W1^T) * dis
__global__ void k_pre1(const float* __restrict__ x, const float* __restrict__ W1, int n) {
    __shared__ float sW[HH * DIN];
    for (int i = threadIdx.x; i < HH * DIN; i += blockDim.x) sW[i] = W1[i];
    __syncthreads();
    int nd = blockIdx.x * blockDim.x + threadIdx.x;
    if (nd >= n) return;
    float xv[DIN];
    const float4* xp = (const float4*)(x + (size_t)nd * DIN);
#pragma unroll
    for (int i = 0; i < DIN / 4; i++) {
        float4 t = xp[i];
        xv[4*i] = t.x; xv[4*i+1] = t.y; xv[4*i+2] = t.z; xv[4*i+3] = t.w;
    }
    float dis = rsqrtf((float)d_cnt[nd] + 1.0f);
    float4* gp = (float4*)(d_G + (size_t)nd * HH);
#pragma unroll
    for (int jq = 0; jq < HH / 4; jq++) {
        float4 v;
        float* vp = (float*)&v;
#pragma unroll
        for (int j = 0; j < 4; j++) {
            float a = 0.f;
#pragma unroll
            for (int i = 0; i < DIN; i++) a = fmaf(xv[i], sW[(jq*4+j) * DIN + i], a);
            vp[j] = a * dis;
        }
        gp[jq] = v;
    }
}

// ======================= vectorized gather core =======================
// Warp per node (4 nodes per warp sequentially). Per iteration the warp
// consumes 4 edges: lane-group g3=lane>>3 handles edge (i*4+g3); each
// lane loads a float4 of the 128B message row (c=lane&7 -> bytes c*16).
// acc float4 per lane; cross-group combine via 2 shfl_xor rounds.
__device__ __forceinline__ float4 gather_row4(const float* __restrict__ Gsrc,
                                              int* sidxw, int start, int end,
                                              int lane, int g3, int c) {
    float4 acc = make_float4(0.f, 0.f, 0.f, 0.f);
    for (int b = start; b < end; b += 32) {
        int j = b + lane;
        sidxw[lane] = (j < end) ? d_csr[j] : 0;
        __syncwarp();
        int m = end - b;
        if (m >= 32) {
#pragma unroll
            for (int i = 0; i < 8; i++) {
                int s = sidxw[i * 4 + g3];
                float4 v = *(const float4*)(Gsrc + (size_t)s * HH + c * 4);
                acc.x += v.x; acc.y += v.y; acc.z += v.z; acc.w += v.w;
            }
        } else {
#pragma unroll
            for (int i = 0; i < 8; i++) {
                int eo = i * 4 + g3;
                if (eo < m) {
                    int s = sidxw[eo];
                    float4 v = *(const float4*)(Gsrc + (size_t)s * HH + c * 4);
                    acc.x += v.x; acc.y += v.y; acc.z += v.z; acc.w += v.w;
                }
            }
        }
        __syncwarp();
    }
    // combine the 4 lane-groups
#pragma unroll
    for (int d = 8; d <= 16; d <<= 1) {
        acc.x += __shfl_xor_sync(0xffffffffu, acc.x, d);
        acc.y += __shfl_xor_sync(0xffffffffu, acc.y, d);
        acc.z += __shfl_xor_sync(0xffffffffu, acc.z, d);
        acc.w += __shfl_xor_sync(0xffffffffu, acc.w, d);
    }
    return acc;
}

// ---------------------------------------------------------------- layer-1 gather + mid transform
// acc = G[node] + sum G[neighbors]; t = tanh(dis*acc + b1); G2 = (t @ W2^T)*dis
__global__ void __launch_bounds__(512) k_gmid2(const float* __restrict__ b1,
                                               const float* __restrict__ W2) {
    __shared__ float sWt[HH * HH];       // sWt[k*32+j] = W2[j*32+k]
    __shared__ float sb[HH];
    __shared__ int   sidx[16][32];
    __shared__ float st[16][HH];
    for (int i = threadIdx.x; i < HH * HH; i += blockDim.x)
        sWt[(i % HH) * HH + (i / HH)] = W2[i];
    if (threadIdx.x < HH) sb[threadIdx.x] = b1[threadIdx.x];
    __syncthreads();

    int wid  = threadIdx.x >> 5;
    int lane = threadIdx.x & 31;
    int g3   = lane >> 3;
    int c    = lane & 7;

    for (int nn = 0; nn < 4; nn++) {
        int node  = blockIdx.x * 64 + wid * 4 + nn;
        int start = d_rowptr[node];
        int end   = d_rowptr[node + 1];
        float dis = rsqrtf((float)(end - start) + 1.0f);

        float4 acc = gather_row4(d_G, sidx[wid], start, end, lane, g3, c);
        // self loop
        float4 sv = *(const float4*)(d_G + (size_t)node * HH + c * 4);
        acc.x += sv.x; acc.y += sv.y; acc.z += sv.z; acc.w += sv.w;

        if (g3 == 0) {
            float4 t;
            t.x = tanhf(fmaf(dis, acc.x, sb[4*c+0]));
            t.y = tanhf(fmaf(dis, acc.y, sb[4*c+1]));
            t.z = tanhf(fmaf(dis, acc.z, sb[4*c+2]));
            t.w = tanhf(fmaf(dis, acc.w, sb[4*c+3]));
            *(float4*)&st[wid][4*c] = t;
        }
        __syncwarp();
        float a = 0.f;
#pragma unroll
        for (int k = 0; k < HH; k++)
            a = fmaf(st[wid][k], sWt[k * HH + lane], a);
        d_G2[(size_t)node * HH + lane] = a * dis;
        __syncwarp();
    }
}

// ---------------------------------------------------------------- layer-2 gather + post transform + pool
__global__ void __launch_bounds__(512) k_gpost2(const float* __restrict__ b2,
                                                const float* __restrict__ Wl,
                                                const float* __restrict__ bl) {
    __shared__ float sWt[HH * HH];
    __shared__ float sb2[HH];
    __shared__ float sbl[HH];
    __shared__ int   sidx[16][32];
    __shared__ float st[16][HH];
    __shared__ float spool[HH];
    for (int i = threadIdx.x; i < HH * HH; i += blockDim.x)
        sWt[(i % HH) * HH + (i / HH)] = Wl[i];
    if (threadIdx.x < HH) {
        sb2[threadIdx.x] = b2[threadIdx.x];
        sbl[threadIdx.x] = bl[threadIdx.x];
        spool[threadIdx.x] = 0.f;
    }
    __syncthreads();

    int wid  = threadIdx.x >> 5;
    int lane = threadIdx.x & 31;
    int g3   = lane >> 3;
    int c    = lane & 7;

    float vsum = 0.f;
    for (int nn = 0; nn < 4; nn++) {
        int node  = blockIdx.x * 64 + wid * 4 + nn;
        int start = d_rowptr[node];
        int end   = d_rowptr[node + 1];
        float dis = rsqrtf((float)(end - start) + 1.0f);

        float4 acc = gather_row4(d_G2, sidx[wid], start, end, lane, g3, c);
        float4 sv = *(const float4*)(d_G2 + (size_t)node * HH + c * 4);
        acc.x += sv.x; acc.y += sv.y; acc.z += sv.z; acc.w += sv.w;

        if (g3 == 0) {
            float4 u;
            u.x = tanhf(fmaf(dis, acc.x, sb2[4*c+0]));
            u.y = tanhf(fmaf(dis, acc.y, sb2[4*c+1]));
            u.z = tanhf(fmaf(dis, acc.z, sb2[4*c+2]));
            u.w = tanhf(fmaf(dis, acc.w, sb2[4*c+3]));
            *(float4*)&st[wid][4*c] = u;
        }
        __syncwarp();
        float a = sbl[lane];
#pragma unroll
        for (int k = 0; k < HH; k++)
            a = fmaf(st[wid][k], sWt[k * HH + lane], a);
        vsum += tanhf(a);
        __syncwarp();
    }
    atomicAdd(&spool[lane], vsum);
    __syncthreads();
    if (threadIdx.x < HH) {
        int g = blockIdx.x >> 4;    // 64 nodes per CTA, 1024 per graph
        atomicAdd(&d_pool[g * HH + threadIdx.x], spool[threadIdx.x]);
    }
}

// ---------------------------------------------------------------- heads (tiny)
__global__ void k_head(const float* __restrict__ share,
                       const float* __restrict__ Wp, const float* __restrict__ bp,
                       const float* __restrict__ Vw1, const float* __restrict__ Vb1,
                       const float* __restrict__ Vw2, const float* __restrict__ Vb2,
                       const float* __restrict__ Vw3, const float* __restrict__ Vb3,
                       const float* __restrict__ Cw1, const float* __restrict__ Cb1,
                       const float* __restrict__ Cw2, const float* __restrict__ Cb2,
                       float* __restrict__ out) {
    int b = threadIdx.x;
    if (b >= BB) return;
    float p[HH];
#pragma unroll
    for (int k = 0; k < HH; k++) p[k] = d_pool[b * HH + k];
    float h1[HH];
#pragma unroll
    for (int j = 0; j < HH; j++) {
        float a = bp[j];
#pragma unroll
        for (int k = 0; k < HH; k++) a = fmaf(p[k], Wp[j * HH + k], a);
        h1[j] = a;
    }
    float s[2 * HH];
#pragma unroll
    for (int k = 0; k < 2 * HH; k++) s[k] = share[b * 2 * HH + k];
    float a1[HH];
#pragma unroll
    for (int j = 0; j < HH; j++) {
        float a = Vb1[j];
#pragma unroll
        for (int k = 0; k < 2 * HH; k++) a = fmaf(s[k], Vw1[j * 2 * HH + k], a);
        a1[j] = tanhf(a);
    }
    float a2[HH];
#pragma unroll
    for (int j = 0; j < HH; j++) {
        float a = Vb2[j];
#pragma unroll
        for (int k = 0; k < HH; k++) a = fmaf(a1[k], Vw2[j * HH + k], a);
        a2[j] = tanhf(a);
    }
    float h2[HH];
#pragma unroll
    for (int j = 0; j < HH; j++) {
        float a = Vb3[j];
#pragma unroll
        for (int k = 0; k < HH; k++) a = fmaf(a2[k], Vw3[j * HH + k], a);
        h2[j] = a;
    }
    float val = Cb2[0];
#pragma unroll
    for (int j = 0; j < HH; j++) {
        float a = Cb1[j];
#pragma unroll
        for (int k = 0; k < HH; k++) a = fmaf(h1[k], Cw1[j * 2 * HH + k], a);
#pragma unroll
        for (int k = 0; k < HH; k++) a = fmaf(h2[k], Cw1[j * 2 * HH + HH + k], a);
        val = fmaf(tanhf(a), Cw2[j], val);
    }
    out[b] = val;
}

extern "C" void kernel_launch(void* const* d_in, const int* in_sizes, int n_in,
                              void* d_out, int out_size) {
    const float* x     = (const float*)d_in[0];
    const int*   ei    = (const int*)  d_in[1];
    const float* share = (const float*)d_in[3];
    const float* W1  = (const float*)d_in[4];
    const float* b1  = (const float*)d_in[5];
    const float* W2  = (const float*)d_in[6];
    const float* b2  = (const float*)d_in[7];
    const float* Wl  = (const float*)d_in[8];
    const float* bl  = (const float*)d_in[9];
    const float* Wp  = (const float*)d_in[10];
    const float* bp  = (const float*)d_in[11];
    const float* Vw1 = (const float*)d_in[12];
    const float* Vb1 = (const float*)d_in[13];
    const float* Vw2 = (const float*)d_in[14];
    const float* Vb2 = (const float*)d_in[15];
    const float* Vw3 = (const float*)d_in[16];
    const float* Vb3 = (const float*)d_in[17];
    const float* Cw1 = (const float*)d_in[18];
    const float* Cb1 = (const float*)d_in[19];
    const float* Cw2 = (const float*)d_in[20];
    const float* Cb2 = (const float*)d_in[21];

    int n = in_sizes[0] / DIN;          // 65536
    int e = in_sizes[1] / 2;            // 2097152
    const int* src = ei;
    const int* dst = ei + e;

    int nb = (n + 255) / 256;
    int eb = (e + 255) / 256;

    k_zero  <<<nb, 256>>>(n);
    k_count <<<eb, 256>>>(dst, e);
    k_scan  <<<1, 1024>>>();
    k_fill  <<<eb, 256>>>(src, dst, e);
    k_pre1  <<<nb, 256>>>(x, W1, n);
    k_gmid2 <<<n / 64, 512>>>(b1, W2);
    k_gpost2<<<n / 64, 512>>>(b2, Wl, bl);
    k_head  <<<1, 64>>>(share, Wp, bp, Vw1, Vb1, Vw2, Vb2, Vw3, Vb3,
                        Cw1, Cb1, Cw2, Cb2, (float*)d_out);
}

// round 5
// speedup vs baseline: 1.7563x; 1.1073x over previous
#include <cuda_runtime.h>

#define NN   65536
#define PP   1024
#define BB   64
#define HH   32
#define DIN  16
#define EE   2097152

#define BCTA   512                 // binning CTAs
#define BEDGE  (EE / BCTA)         // 4096 edges per binning CTA
#define BINCAP 128                 // smem bin capacity (mean 64, +8 sigma)
#define GSTRIDE 36864              // per-graph edge-bin stride (mean 32768, +22 sigma)
#define HSTRIDE 18432              // per-half CSR stride (mean 16384, +16 sigma)

// ---------------- device scratch (no allocation allowed) ----------------
__device__ int            d_bcnt[BCTA * BB];
__device__ int            d_base[BCTA * BB];
__device__ int            d_gtot[BB];
__device__ __align__(16) int d_binE[BB * GSTRIDE];     // packed (dst_local<<10|src_local)
__device__ __align__(16) unsigned short d_csrH[128 * HSTRIDE];
__device__ __align__(16) int   d_rpH[128 * 513];
__device__ __align__(16) float d_G [NN * HH];
__device__ __align__(16) float d_G2[NN * HH];
__device__ __align__(16) float d_pool[BB * HH];

__device__ __forceinline__ float ftanh(float x) {
    float e = __expf(2.0f * x);
    return 1.0f - __fdividef(2.0f, e + 1.0f);
}

// ---------------- binning: count per (cta, graph) ----------------
__global__ void k_bc(const int* __restrict__ dst) {
    __shared__ int h[BB];
    int t = threadIdx.x;
    if (t < BB) h[t] = 0;
    __syncthreads();
    int base = blockIdx.x * BEDGE;
    for (int i = t; i < BEDGE; i += 256)
        atomicAdd(&h[dst[base + i] >> 10], 1);
    __syncthreads();
    if (t < BB) d_bcnt[blockIdx.x * BB + t] = h[t];
}

// ---------------- binning: scan per-graph over CTAs (deterministic) ----------------
__global__ void k_bscan() {
    int t = threadIdx.x;               // 1024 threads
    for (int i = t; i < BB * HH; i += 1024) d_pool[i] = 0.0f;
    int w = t >> 5, lane = t & 31;
    for (int g = w; g < BB; g += 32) {
        int loc[16]; int s = 0;
        int c0 = lane * 16;
#pragma unroll
        for (int i = 0; i < 16; i++) { loc[i] = d_bcnt[(c0 + i) * BB + g]; s += loc[i]; }
        int run = s;
#pragma unroll
        for (int off = 1; off < 32; off <<= 1) {
            int v = __shfl_up_sync(0xffffffffu, run, off);
            if (lane >= off) run += v;
        }
        int excl = run - s;
        int b = g * GSTRIDE + excl;
#pragma unroll
        for (int i = 0; i < 16; i++) { d_base[(c0 + i) * BB + g] = b; b += loc[i]; }
        if (lane == 31) d_gtot[g] = run;
    }
}

// ---------------- binning: smem-stage + coalesced flush ----------------
__global__ void k_bfill(const int* __restrict__ src, const int* __restrict__ dst) {
    __shared__ int bins[BB][BINCAP];
    __shared__ int cur[BB];
    int t = threadIdx.x;
    if (t < BB) cur[t] = 0;
    __syncthreads();
    int base = blockIdx.x * BEDGE;
    for (int i = t; i < BEDGE; i += 256) {
        int s = src[base + i], d = dst[base + i];
        int g = d >> 10;
        int p = atomicAdd(&cur[g], 1);
        if (p < BINCAP) bins[g][p] = ((d & 1023) << 10) | (s & 1023);
    }
    __syncthreads();
    int w = t >> 5, lane = t & 31;
    for (int g = w; g < BB; g += 8) {
        int m = cur[g]; if (m > BINCAP) m = BINCAP;
        int gb = d_base[blockIdx.x * BB + g];
        for (int i = lane; i < m; i += 32)
            d_binE[gb + i] = bins[g][i];
    }
}

// ---------------- A: per-half local CSR build + message compute ----------------
__global__ void __launch_bounds__(512) k_A(const float* __restrict__ x,
                                           const float* __restrict__ W1) {
    extern __shared__ int smA[];
    int* sE   = smA;                                   // GSTRIDE ints
    int* sCnt = sE + GSTRIDE;                          // 512
    int* sRow = sCnt + 512;                            // 513
    unsigned short* sCsr = (unsigned short*)(sRow + 516);
    float* sW = (float*)(sCsr + HSTRIDE);

    int t = threadIdx.x;
    int g = blockIdx.x >> 1, h = blockIdx.x & 1;
    int tot = d_gtot[g];

    const int* bin = d_binE + g * GSTRIDE;
    for (int i = t; i < tot; i += 512) sE[i] = bin[i];
    if (t < 512) sCnt[t] = 0;
    for (int i = t; i < HH * DIN; i += 512)
        sW[(i & 15) * HH + (i >> 4)] = W1[i];
    __syncthreads();

    for (int i = t; i < tot; i += 512) {
        int e = sE[i]; int dl = e >> 10;
        if ((dl >> 9) == h) atomicAdd(&sCnt[dl & 511], 1);
    }
    __syncthreads();
    if (t < 32) {
        int loc[16]; int s = 0;
#pragma unroll
        for (int i = 0; i < 16; i++) { loc[i] = sCnt[t * 16 + i]; s += loc[i]; }
        int run = s;
#pragma unroll
        for (int off = 1; off < 32; off <<= 1) {
            int v = __shfl_up_sync(0xffffffffu, run, off);
            if (t >= off) run += v;
        }
        int excl = run - s;
#pragma unroll
        for (int i = 0; i < 16; i++) { sRow[t * 16 + i] = excl; excl += loc[i]; }
        if (t == 31) sRow[512] = excl;
    }
    __syncthreads();
    if (t < 512) sCnt[t] = sRow[t];
    __syncthreads();
    for (int i = t; i < tot; i += 512) {
        int e = sE[i]; int dl = e >> 10;
        if ((dl >> 9) == h) {
            int p = atomicAdd(&sCnt[dl & 511], 1);
            sCsr[p] = (unsigned short)(e & 1023);
        }
    }
    __syncthreads();

    int half = blockIdx.x;
    int m = sRow[512];
    int* gcsr = (int*)(d_csrH + (size_t)half * HSTRIDE);
    const int* scsri = (const int*)sCsr;
    for (int i = t; i < (m + 1) / 2; i += 512) gcsr[i] = scsri[i];
    for (int i = t; i < 513; i += 512) d_rpH[half * 513 + i] = sRow[i];

    {
        int nl = t;
        int node = g * PP + (h << 9) + nl;
        float xv[DIN];
        const float4* xp = (const float4*)(x + (size_t)node * DIN);
#pragma unroll
        for (int i = 0; i < DIN / 4; i++) {
            float4 v = xp[i];
            xv[4*i] = v.x; xv[4*i+1] = v.y; xv[4*i+2] = v.z; xv[4*i+3] = v.w;
        }
        float dis = rsqrtf((float)(sRow[nl + 1] - sRow[nl]) + 1.0f);
        float4 a[8];
#pragma unroll
        for (int q = 0; q < 8; q++) a[q] = make_float4(0.f, 0.f, 0.f, 0.f);
        const float4* sW4 = (const float4*)sW;
#pragma unroll
        for (int ii = 0; ii < DIN; ii++) {
            float xi = xv[ii];
#pragma unroll
            for (int q = 0; q < 8; q++) {
                float4 w = sW4[ii * 8 + q];
                a[q].x = fmaf(xi, w.x, a[q].x);
                a[q].y = fmaf(xi, w.y, a[q].y);
                a[q].z = fmaf(xi, w.z, a[q].z);
                a[q].w = fmaf(xi, w.w, a[q].w);
            }
        }
        float4* gp = (float4*)(d_G + (size_t)node * HH);
#pragma unroll
        for (int q = 0; q < 8; q++) {
            a[q].x *= dis; a[q].y *= dis; a[q].z *= dis; a[q].w *= dis;
            gp[q] = a[q];
        }
    }
}

// ---------------- smem gather core (self-loop added AFTER combine) ----------------
__device__ __forceinline__ float4 gatherNode(const float* sG, const unsigned short* sCsr,
                                             int start, int end, int nodeRow,
                                             int lane, int g3, int c) {
    const float4* g4 = (const float4*)sG;
    float4 acc = make_float4(0.f, 0.f, 0.f, 0.f);
    for (int b = start; b < end; b += 32) {
        int j = b + lane;
        int idx = (j < end) ? (int)sCsr[j] : 0;
        int mm = end - b;
        if (mm >= 32) {
#pragma unroll
            for (int i = 0; i < 8; i++) {
                int s = __shfl_sync(0xffffffffu, idx, i * 4 + g3);
                float4 v = g4[s * 8 + c];
                acc.x += v.x; acc.y += v.y; acc.z += v.z; acc.w += v.w;
            }
        } else {
#pragma unroll
            for (int i = 0; i < 8; i++) {
                int eo = i * 4 + g3;
                int s = __shfl_sync(0xffffffffu, idx, eo);
                if (eo < mm) {
                    float4 v = g4[s * 8 + c];
                    acc.x += v.x; acc.y += v.y; acc.z += v.z; acc.w += v.w;
                }
            }
        }
    }
#pragma unroll
    for (int d = 8; d <= 16; d <<= 1) {
        acc.x += __shfl_xor_sync(0xffffffffu, acc.x, d);
        acc.y += __shfl_xor_sync(0xffffffffu, acc.y, d);
        acc.z += __shfl_xor_sync(0xffffffffu, acc.z, d);
        acc.w += __shfl_xor_sync(0xffffffffu, acc.w, d);
    }
    // self loop — added once, after the 4-group combine
    float4 sv = g4[nodeRow * 8 + c];
    acc.x += sv.x; acc.y += sv.y; acc.z += sv.z; acc.w += sv.w;
    return acc;
}

// ---------------- B: layer-1 gather (smem) + W2 transform ----------------
__global__ void __launch_bounds__(512) k_B(const float* __restrict__ b1,
                                           const float* __restrict__ W2) {
    extern __shared__ float smB[];
    float* sG = smB;
    int*   sRp = (int*)(sG + PP * HH);
    unsigned short* sCsr = (unsigned short*)(sRp + 516);
    int t = threadIdx.x;
    int g = blockIdx.x >> 1, h = blockIdx.x & 1;
    int half = blockIdx.x;

    const float4* gs = (const float4*)(d_G + (size_t)g * PP * HH);
    float4* sg4 = (float4*)sG;
    for (int i = t; i < PP * HH / 4; i += 512) sg4[i] = gs[i];
    for (int i = t; i < 513; i += 512) sRp[i] = d_rpH[half * 513 + i];
    __syncthreads();
    int m = sRp[512];
    const int* gcsr = (const int*)(d_csrH + (size_t)half * HSTRIDE);
    int* scsri = (int*)sCsr;
    for (int i = t; i < (m + 1) / 2; i += 512) scsri[i] = gcsr[i];

    int lane = t & 31, w = t >> 5;
    int c = lane & 7, g3 = lane >> 3;
    float4 wr[8];
    const float4* w4 = (const float4*)(W2 + lane * HH);
#pragma unroll
    for (int q = 0; q < 8; q++) wr[q] = w4[q];
    float4 b4 = *(const float4*)(b1 + 4 * c);
    __syncthreads();

    for (int nl = w * 32; nl < w * 32 + 32; nl++) {
        int start = sRp[nl], end = sRp[nl + 1];
        float dis = rsqrtf((float)(end - start) + 1.0f);
        int nodeRow = (h << 9) + nl;
        float4 acc = gatherNode(sG, sCsr, start, end, nodeRow, lane, g3, c);
        float4 tv;
        tv.x = ftanh(fmaf(dis, acc.x, b4.x));
        tv.y = ftanh(fmaf(dis, acc.y, b4.y));
        tv.z = ftanh(fmaf(dis, acc.z, b4.z));
        tv.w = ftanh(fmaf(dis, acc.w, b4.w));
        float o = 0.0f;
#pragma unroll
        for (int kc = 0; kc < 8; kc++) {
            float t0 = __shfl_sync(0xffffffffu, tv.x, kc);
            float t1 = __shfl_sync(0xffffffffu, tv.y, kc);
            float t2 = __shfl_sync(0xffffffffu, tv.z, kc);
            float t3 = __shfl_sync(0xffffffffu, tv.w, kc);
            o = fmaf(t0, wr[kc].x, o);
            o = fmaf(t1, wr[kc].y, o);
            o = fmaf(t2, wr[kc].z, o);
            o = fmaf(t3, wr[kc].w, o);
        }
        d_G2[((size_t)g * PP + nodeRow) * HH + lane] = o * dis;
    }
}

// ---------------- C: layer-2 gather (smem) + Wl transform + pool ----------------
__global__ void __launch_bounds__(512) k_C(const float* __restrict__ b2,
                                           const float* __restrict__ Wl,
                                           const float* __restrict__ bl) {
    extern __shared__ float smC[];
    float* sG = smC;
    int*   sRp = (int*)(sG + PP * HH);
    unsigned short* sCsr = (unsigned short*)(sRp + 516);
    float* sRed = (float*)(sCsr + HSTRIDE);
    int t = threadIdx.x;
    int g = blockIdx.x >> 1, h = blockIdx.x & 1;
    int half = blockIdx.x;

    const float4* gs = (const float4*)(d_G2 + (size_t)g * PP * HH);
    float4* sg4 = (float4*)sG;
    for (int i = t; i < PP * HH / 4; i += 512) sg4[i] = gs[i];
    for (int i = t; i < 513; i += 512) sRp[i] = d_rpH[half * 513 + i];
    __syncthreads();
    int m = sRp[512];
    const int* gcsr = (const int*)(d_csrH + (size_t)half * HSTRIDE);
    int* scsri = (int*)sCsr;
    for (int i = t; i < (m + 1) / 2; i += 512) scsri[i] = gcsr[i];

    int lane = t & 31, w = t >> 5;
    int c = lane & 7, g3 = lane >> 3;
    float4 wr[8];
    const float4* w4 = (const float4*)(Wl + lane * HH);
#pragma unroll
    for (int q = 0; q < 8; q++) wr[q] = w4[q];
    float4 b4 = *(const float4*)(b2 + 4 * c);
    float blr = bl[lane];
    __syncthreads();

    float vsum = 0.0f;
    for (int nl = w * 32; nl < w * 32 + 32; nl++) {
        int start = sRp[nl], end = sRp[nl + 1];
        float dis = rsqrtf((float)(end - start) + 1.0f);
        int nodeRow = (h << 9) + nl;
        float4 acc = gatherNode(sG, sCsr, start, end, nodeRow, lane, g3, c);
        float4 uv;
        uv.x = ftanh(fmaf(dis, acc.x, b4.x));
        uv.y = ftanh(fmaf(dis, acc.y, b4.y));
        uv.z = ftanh(fmaf(dis, acc.z, b4.z));
        uv.w = ftanh(fmaf(dis, acc.w, b4.w));
        float a = blr;
#pragma unroll
        for (int kc = 0; kc < 8; kc++) {
            float t0 = __shfl_sync(0xffffffffu, uv.x, kc);
            float t1 = __shfl_sync(0xffffffffu, uv.y, kc);
            float t2 = __shfl_sync(0xffffffffu, uv.z, kc);
            float t3 = __shfl_sync(0xffffffffu, uv.w, kc);
            a = fmaf(t0, wr[kc].x, a);
            a = fmaf(t1, wr[kc].y, a);
            a = fmaf(t2, wr[kc].z, a);
            a = fmaf(t3, wr[kc].w, a);
        }
        vsum += ftanh(a);
    }
    sRed[w * HH + lane] = vsum;
    __syncthreads();
    if (t < HH) {
        float s = 0.0f;
#pragma unroll
        for (int r = 0; r < 16; r++) s += sRed[r * HH + t];
        atomicAdd(&d_pool[g * HH + t], s);
    }
}

// ---------------- heads ----------------
__global__ void k_head(const float* __restrict__ share,
                       const float* __restrict__ Wp, const float* __restrict__ bp,
                       const float* __restrict__ Vw1, const float* __restrict__ Vb1,
                       const float* __restrict__ Vw2, const float* __restrict__ Vb2,
                       const float* __restrict__ Vw3, const float* __restrict__ Vb3,
                       const float* __restrict__ Cw1, const float* __restrict__ Cb1,
                       const float* __restrict__ Cw2, const float* __restrict__ Cb2,
                       float* __restrict__ out) {
    int b = threadIdx.x;
    if (b >= BB) return;
    float p[HH];
#pragma unroll
    for (int k = 0; k < HH; k++) p[k] = d_pool[b * HH + k];
    float h1[HH];
#pragma unroll
    for (int j = 0; j < HH; j++) {
        float a = bp[j];
#pragma unroll
        for (int k = 0; k < HH; k++) a = fmaf(p[k], Wp[j * HH + k], a);
        h1[j] = a;
    }
    float s[2 * HH];
#pragma unroll
    for (int k = 0; k < 2 * HH; k++) s[k] = share[b * 2 * HH + k];
    float a1[HH];
#pragma unroll
    for (int j = 0; j < HH; j++) {
        float a = Vb1[j];
#pragma unroll
        for (int k = 0; k < 2 * HH; k++) a = fmaf(s[k], Vw1[j * 2 * HH + k], a);
        a1[j] = tanhf(a);
    }
    float a2[HH];
#pragma unroll
    for (int j = 0; j < HH; j++) {
        float a = Vb2[j];
#pragma unroll
        for (int k = 0; k < HH; k++) a = fmaf(a1[k], Vw2[j * HH + k], a);
        a2[j] = tanhf(a);
    }
    float h2[HH];
#pragma unroll
    for (int j = 0; j < HH; j++) {
        float a = Vb3[j];
#pragma unroll
        for (int k = 0; k < HH; k++) a = fmaf(a2[k], Vw3[j * HH + k], a);
        h2[j] = a;
    }
    float val = Cb2[0];
#pragma unroll
    for (int j = 0; j < HH; j++) {
        float a = Cb1[j];
#pragma unroll
        for (int k = 0; k < HH; k++) a = fmaf(h1[k], Cw1[j * 2 * HH + k], a);
#pragma unroll
        for (int k = 0; k < HH; k++) a = fmaf(h2[k], Cw1[j * 2 * HH + HH + k], a);
        val = fmaf(tanhf(a), Cw2[j], val);
    }
    out[b] = val;
}

extern "C" void kernel_launch(void* const* d_in, const int* in_sizes, int n_in,
                              void* d_out, int out_size) {
    const float* x     = (const float*)d_in[0];
    const int*   ei    = (const int*)  d_in[1];
    const float* share = (const float*)d_in[3];
    const float* W1  = (const float*)d_in[4];
    const float* b1  = (const float*)d_in[5];
    const float* W2  = (const float*)d_in[6];
    const float* b2  = (const float*)d_in[7];
    const float* Wl  = (const float*)d_in[8];
    const float* bl  = (const float*)d_in[9];
    const float* Wp  = (const float*)d_in[10];
    const float* bp  = (const float*)d_in[11];
    const float* Vw1 = (const float*)d_in[12];
    const float* Vb1 = (const float*)d_in[13];
    const float* Vw2 = (const float*)d_in[14];
    const float* Vb2 = (const float*)d_in[15];
    const float* Vw3 = (const float*)d_in[16];
    const float* Vb3 = (const float*)d_in[17];
    const float* Cw1 = (const float*)d_in[18];
    const float* Cb1 = (const float*)d_in[19];
    const float* Cw2 = (const float*)d_in[20];
    const float* Cb2 = (const float*)d_in[21];

    int e = in_sizes[1] / 2;
    const int* src = ei;
    const int* dst = ei + e;

    int smA = GSTRIDE * 4 + 512 * 4 + 516 * 4 + HSTRIDE * 2 + HH * DIN * 4;
    int smB = PP * HH * 4 + 516 * 4 + HSTRIDE * 2;
    int smC = smB + 16 * HH * 4 + 16;

    cudaFuncSetAttribute(k_A, cudaFuncAttributeMaxDynamicSharedMemorySize, smA);
    cudaFuncSetAttribute(k_B, cudaFuncAttributeMaxDynamicSharedMemorySize, smB);
    cudaFuncSetAttribute(k_C, cudaFuncAttributeMaxDynamicSharedMemorySize, smC);

    k_bc   <<<BCTA, 256>>>(dst);
    k_bscan<<<1, 1024>>>();
    k_bfill<<<BCTA, 256>>>(src, dst);
    k_A    <<<128, 512, smA>>>(x, W1);
    k_B    <<<128, 512, smB>>>(b1, W2);
    k_C    <<<128, 512, smC>>>(b2, Wl, bl);
    k_head <<<1, 64>>>(share, Wp, bp, Vw1, Vb1, Vw2, Vb2, Vw3, Vb3,
                       Cw1, Cb1, Cw2, Cb2, (float*)d_out);
}

// round 8
// speedup vs baseline: 2.4219x; 1.3790x over previous
#include <cuda_runtime.h>

#define NN   65536
#define PP   1024
#define BB   64
#define HH   32
#define DIN  16
#define EE   2097152

#define BCTA   512                 // binning CTAs
#define BEDGE  (EE / BCTA)         // 4096 edges per binning CTA
#define BINCAP 128                 // smem bin capacity (mean 64, +8 sigma)
#define GSTRIDE 36864              // per-graph edge-bin capacity (mean 32768, +22 sigma)
#define HSTRIDE 18432              // per-half CSR stride (mean 16384, +16 sigma)

// ---------------- device scratch (no allocation allowed) ----------------
__device__ int            d_gcur[BB];
__device__ __align__(16) int d_binE[BB * GSTRIDE];   // packed (dst_local<<10|src_local)
__device__ __align__(16) int d_csrI[128 * HSTRIDE];  // per-half CSR (src_local as int)
__device__ __align__(16) int d_rpH[128 * 513];
__device__ __align__(16) float d_G [NN * HH];
__device__ __align__(16) float d_G2[NN * HH];
__device__ __align__(16) float d_pool[BB * HH];

__device__ __forceinline__ float ftanh(float x) {
    float e = __expf(2.0f * x);
    return 1.0f - __fdividef(2.0f, e + 1.0f);
}

// ---------------- zero cursors + pool ----------------
__global__ void k_z() {
    int t = threadIdx.x;
    if (t < BB) d_gcur[t] = 0;
    for (int i = t; i < BB * HH; i += 1024) d_pool[i] = 0.0f;
}

// ---------------- one-pass binning: smem bins + global reservation ----------------
__global__ void k_bin(const int* __restrict__ src, const int* __restrict__ dst) {
    __shared__ int bins[BB][BINCAP];
    __shared__ int cur[BB];
    __shared__ int gbase[BB];
    int t = threadIdx.x;
    if (t < BB) cur[t] = 0;
    __syncthreads();
    int base = blockIdx.x * BEDGE;
    for (int i = t; i < BEDGE; i += 256) {
        int s = src[base + i], d = dst[base + i];
        int g = d >> 10;
        int pk = ((d & 1023) << 10) | (s & 1023);
        int p = atomicAdd(&cur[g], 1);
        if (p < BINCAP) bins[g][p] = pk;
        else {                                   // rare spill: direct global slot
            int q = atomicAdd(&d_gcur[g], 1);
            d_binE[g * GSTRIDE + q] = pk;
        }
    }
    __syncthreads();
    if (t < BB) {
        int m = cur[t]; if (m > BINCAP) m = BINCAP;
        gbase[t] = atomicAdd(&d_gcur[t], m);
    }
    __syncthreads();
    int w = t >> 5, lane = t & 31;
    for (int g = w; g < BB; g += 8) {
        int m = cur[g]; if (m > BINCAP) m = BINCAP;
        int gb = g * GSTRIDE + gbase[g];
        for (int i = lane; i < m; i += 32)
            d_binE[gb + i] = bins[g][i];
    }
}

// ---------------- A: per-half local CSR build + message compute ----------------
// grid 128 (2 per graph), block 512
__global__ void __launch_bounds__(512) k_A(const float* __restrict__ x,
                                           const float* __restrict__ W1) {
    extern __shared__ int smA[];
    int* sE    = smA;                              // GSTRIDE ints (144KB)
    int* sCnt  = sE + GSTRIDE;                     // 512
    int* sRow  = sCnt + 512;                       // 513 (+3 pad)
    int* sCsrI = sRow + 516;                       // HSTRIDE ints (72KB)
    float* sW  = (float*)(sCsrI + HSTRIDE);        // 16x32 transposed W1

    int t = threadIdx.x;
    int g = blockIdx.x >> 1, h = blockIdx.x & 1;
    int tot = d_gcur[g];

    const int* bin = d_binE + g * GSTRIDE;
    for (int i = t; i < tot; i += 512) sE[i] = bin[i];
    if (t < 512) sCnt[t] = 0;
    for (int i = t; i < HH * DIN; i += 512)
        sW[(i & 15) * HH + (i >> 4)] = W1[i];
    __syncthreads();

    // count my half
    for (int i = t; i < tot; i += 512) {
        int e = sE[i]; int dl = e >> 10;
        if ((dl >> 9) == h) atomicAdd(&sCnt[dl & 511], 1);
    }
    __syncthreads();
    // scan 512 counters
    if (t < 32) {
        int loc[16]; int s = 0;
#pragma unroll
        for (int i = 0; i < 16; i++) { loc[i] = sCnt[t * 16 + i]; s += loc[i]; }
        int run = s;
#pragma unroll
        for (int off = 1; off < 32; off <<= 1) {
            int v = __shfl_up_sync(0xffffffffu, run, off);
            if (t >= off) run += v;
        }
        int excl = run - s;
#pragma unroll
        for (int i = 0; i < 16; i++) { sRow[t * 16 + i] = excl; excl += loc[i]; }
        if (t == 31) sRow[512] = excl;
    }
    __syncthreads();
    if (t < 512) sCnt[t] = sRow[t];
    __syncthreads();
    // fill
    for (int i = t; i < tot; i += 512) {
        int e = sE[i]; int dl = e >> 10;
        if ((dl >> 9) == h) {
            int p = atomicAdd(&sCnt[dl & 511], 1);
            sCsrI[p] = e & 1023;
        }
    }
    __syncthreads();

    // flush CSR + rowptr
    int half = blockIdx.x;
    int m = sRow[512];
    int* gcsr = d_csrI + (size_t)half * HSTRIDE;
    for (int i = t; i < m; i += 512) gcsr[i] = sCsrI[i];
    for (int i = t; i < 513; i += 512) d_rpH[half * 513 + i] = sRow[i];

    // messages: G[node] = (x[node] @ W1^T) * dis
    {
        int nl = t;
        int node = g * PP + (h << 9) + nl;
        float xv[DIN];
        const float4* xp = (const float4*)(x + (size_t)node * DIN);
#pragma unroll
        for (int i = 0; i < DIN / 4; i++) {
            float4 v = xp[i];
            xv[4*i] = v.x; xv[4*i+1] = v.y; xv[4*i+2] = v.z; xv[4*i+3] = v.w;
        }
        float dis = rsqrtf((float)(sRow[nl + 1] - sRow[nl]) + 1.0f);
        float4 a[8];
#pragma unroll
        for (int q = 0; q < 8; q++) a[q] = make_float4(0.f, 0.f, 0.f, 0.f);
        const float4* sW4 = (const float4*)sW;
#pragma unroll
        for (int ii = 0; ii < DIN; ii++) {
            float xi = xv[ii];
#pragma unroll
            for (int q = 0; q < 8; q++) {
                float4 w = sW4[ii * 8 + q];
                a[q].x = fmaf(xi, w.x, a[q].x);
                a[q].y = fmaf(xi, w.y, a[q].y);
                a[q].z = fmaf(xi, w.z, a[q].z);
                a[q].w = fmaf(xi, w.w, a[q].w);
            }
        }
        float4* gp = (float4*)(d_G + (size_t)node * HH);
#pragma unroll
        for (int q = 0; q < 8; q++) {
            a[q].x *= dis; a[q].y *= dis; a[q].z *= dis; a[q].w *= dis;
            gp[q] = a[q];
        }
    }
}

// ---------------- smem gather core: direct LDS index reads, no shfl in loop ----------------
__device__ __forceinline__ float4 gatherNode(const float4* g4, const int* sCsrI,
                                             int start, int end, int nodeRow,
                                             int g3, int c) {
    float4 acc = make_float4(0.f, 0.f, 0.f, 0.f);
    int b = start;
    for (; b + 32 <= end; b += 32) {
#pragma unroll
        for (int i = 0; i < 8; i++) {
            int s = sCsrI[b + i * 4 + g3];       // broadcast within 8-lane quarter
            float4 v = g4[s * 8 + c];
            acc.x += v.x; acc.y += v.y; acc.z += v.z; acc.w += v.w;
        }
    }
    for (int j = b + g3; j < end; j += 4) {      // remainder, quarter-partitioned
        int s = sCsrI[j];
        float4 v = g4[s * 8 + c];
        acc.x += v.x; acc.y += v.y; acc.z += v.z; acc.w += v.w;
    }
#pragma unroll
    for (int d = 8; d <= 16; d <<= 1) {
        acc.x += __shfl_xor_sync(0xffffffffu, acc.x, d);
        acc.y += __shfl_xor_sync(0xffffffffu, acc.y, d);
        acc.z += __shfl_xor_sync(0xffffffffu, acc.z, d);
        acc.w += __shfl_xor_sync(0xffffffffu, acc.w, d);
    }
    float4 sv = g4[nodeRow * 8 + c];             // self loop, once, after combine
    acc.x += sv.x; acc.y += sv.y; acc.z += sv.z; acc.w += sv.w;
    return acc;
}

// ---------------- B: layer-1 gather + W2 transform ----------------
__global__ void __launch_bounds__(1024) k_B(const float* __restrict__ b1,
                                            const float* __restrict__ W2) {
    extern __shared__ float smB[];
    float* sG   = smB;                            // 1024*32 floats (128KB)
    int*   sRp  = (int*)(sG + PP * HH);           // 513 (+3)
    int*   sCsrI= sRp + 516;                      // HSTRIDE ints (72KB)
    int t = threadIdx.x;
    int g = blockIdx.x >> 1, h = blockIdx.x & 1, half = blockIdx.x;

    const float4* gs = (const float4*)(d_G + (size_t)g * PP * HH);
    float4* sg4 = (float4*)sG;
    for (int i = t; i < PP * HH / 4; i += 1024) sg4[i] = gs[i];
    for (int i = t; i < 513; i += 1024) sRp[i] = d_rpH[half * 513 + i];
    __syncthreads();
    int m = sRp[512];
    const int* gcsr = d_csrI + (size_t)half * HSTRIDE;
    for (int i = t; i < m; i += 1024) sCsrI[i] = gcsr[i];

    int lane = t & 31, w = t >> 5;
    int c = lane & 7, g3 = lane >> 3;
    float4 wr[8];
    const float4* w4 = (const float4*)(W2 + lane * HH);
#pragma unroll
    for (int q = 0; q < 8; q++) wr[q] = w4[q];
    float4 b4 = *(const float4*)(b1 + 4 * c);
    __syncthreads();

    const float4* g4 = (const float4*)sG;
    for (int nl = w * 16; nl < w * 16 + 16; nl++) {
        int start = sRp[nl], end = sRp[nl + 1];
        float dis = rsqrtf((float)(end - start) + 1.0f);
        int nodeRow = (h << 9) + nl;
        float4 acc = gatherNode(g4, sCsrI, start, end, nodeRow, g3, c);
        float4 tv;
        tv.x = ftanh(fmaf(dis, acc.x, b4.x));
        tv.y = ftanh(fmaf(dis, acc.y, b4.y));
        tv.z = ftanh(fmaf(dis, acc.z, b4.z));
        tv.w = ftanh(fmaf(dis, acc.w, b4.w));
        float o = 0.0f;
#pragma unroll
        for (int kc = 0; kc < 8; kc++) {
            float t0 = __shfl_sync(0xffffffffu, tv.x, kc);
            float t1 = __shfl_sync(0xffffffffu, tv.y, kc);
            float t2 = __shfl_sync(0xffffffffu, tv.z, kc);
            float t3 = __shfl_sync(0xffffffffu, tv.w, kc);
            o = fmaf(t0, wr[kc].x, o);
            o = fmaf(t1, wr[kc].y, o);
            o = fmaf(t2, wr[kc].z, o);
            o = fmaf(t3, wr[kc].w, o);
        }
        d_G2[((size_t)g * PP + nodeRow) * HH + lane] = o * dis;
    }
}

// ---------------- C: layer-2 gather + Wl transform + pool ----------------
__global__ void __launch_bounds__(1024) k_C(const float* __restrict__ b2,
                                            const float* __restrict__ Wl,
                                            const float* __restrict__ bl) {
    extern __shared__ float smC[];
    float* sG   = smC;
    int*   sRp  = (int*)(sG + PP * HH);
    int*   sCsrI= sRp + 516;
    float* sRed = (float*)(sCsrI + HSTRIDE);      // 32*32 floats
    int t = threadIdx.x;
    int g = blockIdx.x >> 1, h = blockIdx.x & 1, half = blockIdx.x;

    const float4* gs = (const float4*)(d_G2 + (size_t)g * PP * HH);
    float4* sg4 = (float4*)sG;
    for (int i = t; i < PP * HH / 4; i += 1024) sg4[i] = gs[i];
    for (int i = t; i < 513; i += 1024) sRp[i] = d_rpH[half * 513 + i];
    __syncthreads();
    int m = sRp[512];
    const int* gcsr = d_csrI + (size_t)half * HSTRIDE;
    for (int i = t; i < m; i += 1024) sCsrI[i] = gcsr[i];

    int lane = t & 31, w = t >> 5;
    int c = lane & 7, g3 = lane >> 3;
    float4 wr[8];
    const float4* w4 = (const float4*)(Wl + lane * HH);
#pragma unroll
    for (int q = 0; q < 8; q++) wr[q] = w4[q];
    float4 b4 = *(const float4*)(b2 + 4 * c);
    float blr = bl[lane];
    __syncthreads();

    const float4* g4 = (const float4*)sG;
    float vsum = 0.0f;
    for (int nl = w * 16; nl < w * 16 + 16; nl++) {
        int start = sRp[nl], end = sRp[nl + 1];
        float dis = rsqrtf((float)(end - start) + 1.0f);
        int nodeRow = (h << 9) + nl;
        float4 acc = gatherNode(g4, sCsrI, start, end, nodeRow, g3, c);
        float4 uv;
        uv.x = ftanh(fmaf(dis, acc.x, b4.x));
        uv.y = ftanh(fmaf(dis, acc.y, b4.y));
        uv.z = ftanh(fmaf(dis, acc.z, b4.z));
        uv.w = ftanh(fmaf(dis, acc.w, b4.w));
        float a = blr;
#pragma unroll
        for (int kc = 0; kc < 8; kc++) {
            float t0 = __shfl_sync(0xffffffffu, uv.x, kc);
            float t1 = __shfl_sync(0xffffffffu, uv.y, kc);
            float t2 = __shfl_sync(0xffffffffu, uv.z, kc);
            float t3 = __shfl_sync(0xffffffffu, uv.w, kc);
            a = fmaf(t0, wr[kc].x, a);
            a = fmaf(t1, wr[kc].y, a);
            a = fmaf(t2, wr[kc].z, a);
            a = fmaf(t3, wr[kc].w, a);
        }
        vsum += ftanh(a);
    }
    sRed[w * HH + lane] = vsum;
    __syncthreads();
    if (t < HH) {
        float s = 0.0f;
#pragma unroll
        for (int r = 0; r < 32; r++) s += sRed[r * HH + t];
        atomicAdd(&d_pool[g * HH + t], s);
    }
}

// ---------------- heads ----------------
__global__ void k_head(const float* __restrict__ share,
                       const float* __restrict__ Wp, const float* __restrict__ bp,
                       const float* __restrict__ Vw1, const float* __restrict__ Vb1,
                       const float* __restrict__ Vw2, const float* __restrict__ Vb2,
                       const float* __restrict__ Vw3, const float* __restrict__ Vb3,
                       const float* __restrict__ Cw1, const float* __restrict__ Cb1,
                       const float* __restrict__ Cw2, const float* __restrict__ Cb2,
                       float* __restrict__ out) {
    int b = threadIdx.x;
    if (b >= BB) return;
    float p[HH];
#pragma unroll
    for (int k = 0; k < HH; k++) p[k] = d_pool[b * HH + k];
    float h1[HH];
#pragma unroll
    for (int j = 0; j < HH; j++) {
        float a = bp[j];
#pragma unroll
        for (int k = 0; k < HH; k++) a = fmaf(p[k], Wp[j * HH + k], a);
        h1[j] = a;
    }
    float s[2 * HH];
#pragma unroll
    for (int k = 0; k < 2 * HH; k++) s[k] = share[b * 2 * HH + k];
    float a1[HH];
#pragma unroll
    for (int j = 0; j < HH; j++) {
        float a = Vb1[j];
#pragma unroll
        for (int k = 0; k < 2 * HH; k++) a = fmaf(s[k], Vw1[j * 2 * HH + k], a);
        a1[j] = tanhf(a);
    }
    float a2[HH];
#pragma unroll
    for (int j = 0; j < HH; j++) {
        float a = Vb2[j];
#pragma unroll
        for (int k = 0; k < HH; k++) a = fmaf(a1[k], Vw2[j * HH + k], a);
        a2[j] = tanhf(a);
    }
    float h2[HH];
#pragma unroll
    for (int j = 0; j < HH; j++) {
        float a = Vb3[j];
#pragma unroll
        for (int k = 0; k < HH; k++) a = fmaf(a2[k], Vw3[j * HH + k], a);
        h2[j] = a;
    }
    float val = Cb2[0];
#pragma unroll
    for (int j = 0; j < HH; j++) {
        float a = Cb1[j];
#pragma unroll
        for (int k = 0; k < HH; k++) a = fmaf(h1[k], Cw1[j * 2 * HH + k], a);
#pragma unroll
        for (int k = 0; k < HH; k++) a = fmaf(h2[k], Cw1[j * 2 * HH + HH + k], a);
        val = fmaf(tanhf(a), Cw2[j], val);
    }
    out[b] = val;
}

extern "C" void kernel_launch(void* const* d_in, const int* in_sizes, int n_in,
                              void* d_out, int out_size) {
    const float* x     = (const float*)d_in[0];
    const int*   ei    = (const int*)  d_in[1];
    const float* share = (const float*)d_in[3];
    const float* W1  = (const float*)d_in[4];
    const float* b1  = (const float*)d_in[5];
    const float* W2  = (const float*)d_in[6];
    const float* b2  = (const float*)d_in[7];
    const float* Wl  = (const float*)d_in[8];
    const float* bl  = (const float*)d_in[9];
    const float* Wp  = (const float*)d_in[10];
    const float* bp  = (const float*)d_in[11];
    const float* Vw1 = (const float*)d_in[12];
    const float* Vb1 = (const float*)d_in[13];
    const float* Vw2 = (const float*)d_in[14];
    const float* Vb2 = (const float*)d_in[15];
    const float* Vw3 = (const float*)d_in[16];
    const float* Vb3 = (const float*)d_in[17];
    const float* Cw1 = (const float*)d_in[18];
    const float* Cb1 = (const float*)d_in[19];
    const float* Cw2 = (const float*)d_in[20];
    const float* Cb2 = (const float*)d_in[21];

    int e = in_sizes[1] / 2;
    const int* src = ei;
    const int* dst = ei + e;

    int smA = GSTRIDE * 4 + 512 * 4 + 516 * 4 + HSTRIDE * 4 + HH * DIN * 4;  // 227,344
    int smB = PP * HH * 4 + 516 * 4 + HSTRIDE * 4;                            // 206,864
    int smC = smB + 32 * HH * 4;                                              // 210,960

    cudaFuncSetAttribute(k_A, cudaFuncAttributeMaxDynamicSharedMemorySize, smA);
    cudaFuncSetAttribute(k_B, cudaFuncAttributeMaxDynamicSharedMemorySize, smB);
    cudaFuncSetAttribute(k_C, cudaFuncAttributeMaxDynamicSharedMemorySize, smC);

    k_z   <<<1, 1024>>>();
    k_bin <<<BCTA, 256>>>(src, dst);
    k_A   <<<128, 512, smA>>>(x, W1);
    k_B   <<<128, 1024, smB>>>(b1, W2);
    k_C   <<<128, 1024, smC>>>(b2, Wl, bl);
    k_head<<<1, 64>>>(share, Wp, bp, Vw1, Vb1, Vw2, Vb2, Vw3, Vb3,
                      Cw1, Cb1, Cw2, Cb2, (float*)d_out);
}